// round 10
// baseline (speedup 1.0000x reference)
#include <cuda_runtime.h>
#include <cuda_bf16.h>

typedef unsigned int u32;

#define NTOK 16384
#define DDIM 2048
#define NEXP 64
#define TMB  64              // tokens per CTA
#define NBLK (NTOK/TMB)      // 256
#define LSTR 66
#define KSTEPS 64            // k16 steps per k-half (1024/16)
#define TAU   1e-4f

// pack (v0 -> low half, v1 -> high half)
static __device__ __forceinline__ u32 pack_bf16(float v0, float v1) {
    u32 r; asm("cvt.rn.bf16x2.f32 %0, %1, %2;" : "=r"(r) : "f"(v1), "f"(v0)); return r;
}
// split float2 -> (hi bf16x2, lo bf16x2)
static __device__ __forceinline__ void split2(float2 v, u32& hi, u32& lo) {
    hi = pack_bf16(v.x, v.y);
    float f0 = __uint_as_float(hi << 16);
    float f1 = __uint_as_float(hi & 0xffff0000u);
    lo = pack_bf16(v.x - f0, v.y - f1);
}

#define MMA16816(d, a0,a1,a2,a3, b0, b1) \
    asm volatile("mma.sync.aligned.m16n8k16.row.col.f32.bf16.bf16.f32 " \
        "{%0,%1,%2,%3}, {%4,%5,%6,%7}, {%8,%9}, {%0,%1,%2,%3};" \
        : "+f"((d)[0]),"+f"((d)[1]),"+f"((d)[2]),"+f"((d)[3]) \
        : "r"(a0),"r"(a1),"r"(a2),"r"(a3),"r"(b0),"r"(b1))

__global__ __launch_bounds__(256, 2) void moe_main(
    const float* __restrict__ x,
    const float* __restrict__ W,
    const float* __restrict__ sc,
    const float* __restrict__ noise,
    const int*   __restrict__ sidx_p,
    float*       __restrict__ out,
    int do_probs, int do_idx)
{
    __shared__ float lg[2 * TMB * LSTR];   // per-k-half partial logits

    const int t   = threadIdx.x;
    const int wid = t >> 5;
    const int lid = t & 31;

    const int khalf = wid >> 2;            // 0 or 1: k-range [khalf*1024, +1024)
    const int m0    = ((wid >> 1) & 1) * 32;
    const int n0    = (wid & 1) * 32;

    const int r  = lid >> 2;               // fragment row within m8/n8
    const int c0 = (lid & 3) * 2;          // fragment k pair base

    // A row pointers: rows m0+r (+8, +16, +24), k base = khalf*1024 + c0
    const float* xbase = x + (long)blockIdx.x * TMB * DDIM + khalf * 1024 + c0;
    const float* arp[4];
#pragma unroll
    for (int i = 0; i < 4; ++i) arp[i] = xbase + (long)(m0 + r + i * 8) * DDIM;

    // B row pointers: experts n0 + (lid>>2) + nt*8
    const float* wbase = W + khalf * 1024 + c0;
    const float* wrp[4];
#pragma unroll
    for (int i = 0; i < 4; ++i) wrp[i] = wbase + (long)(n0 + (lid >> 2) + i * 8) * DDIM;

    float acc[2][4][4];
#pragma unroll
    for (int mt = 0; mt < 2; ++mt)
#pragma unroll
        for (int nt = 0; nt < 4; ++nt)
#pragma unroll
            for (int q = 0; q < 4; ++q) acc[mt][nt][q] = 0.0f;

    // A raw buffer for current step (prefetched)
    float2 ab[8];
#pragma unroll
    for (int mt = 0; mt < 2; ++mt) {
        ab[mt * 4 + 0] = *(const float2*)(arp[mt * 2 + 0]);
        ab[mt * 4 + 1] = *(const float2*)(arp[mt * 2 + 1]);
        ab[mt * 4 + 2] = *(const float2*)(arp[mt * 2 + 0] + 8);
        ab[mt * 4 + 3] = *(const float2*)(arp[mt * 2 + 1] + 8);
    }

#pragma unroll 2
    for (int s = 0; s < KSTEPS; ++s) {
        const int k = s * 16;

        // 1) issue all B loads for this step (mostly L2 hits)
        float2 brw[8];
#pragma unroll
        for (int nt = 0; nt < 4; ++nt) {
            brw[nt * 2 + 0] = *(const float2*)(wrp[nt] + k);
            brw[nt * 2 + 1] = *(const float2*)(wrp[nt] + k + 8);
        }

        // 2) convert A (from prefetch buffer)
        u32 ah[2][4], al[2][4];
#pragma unroll
        for (int mt = 0; mt < 2; ++mt)
#pragma unroll
            for (int q = 0; q < 4; ++q)
                split2(ab[mt * 4 + q], ah[mt][q], al[mt][q]);

        // 3) prefetch A for next step (lands under the MMA block)
        if (s + 1 < KSTEPS) {
            const int kn = k + 16;
#pragma unroll
            for (int mt = 0; mt < 2; ++mt) {
                ab[mt * 4 + 0] = *(const float2*)(arp[mt * 2 + 0] + kn);
                ab[mt * 4 + 1] = *(const float2*)(arp[mt * 2 + 1] + kn);
                ab[mt * 4 + 2] = *(const float2*)(arp[mt * 2 + 0] + kn + 8);
                ab[mt * 4 + 3] = *(const float2*)(arp[mt * 2 + 1] + kn + 8);
            }
        }

        // 4) convert B per n8 tile and issue MMAs
#pragma unroll
        for (int nt = 0; nt < 4; ++nt) {
            u32 bh0, bh1, bl0, bl1;
            split2(brw[nt * 2 + 0], bh0, bl0);
            split2(brw[nt * 2 + 1], bh1, bl1);
#pragma unroll
            for (int mt = 0; mt < 2; ++mt) {
                MMA16816(acc[mt][nt], ah[mt][0], ah[mt][1], ah[mt][2], ah[mt][3], bh0, bh1); // hi*hi
                MMA16816(acc[mt][nt], ah[mt][0], ah[mt][1], ah[mt][2], ah[mt][3], bl0, bl1); // hi*lo
                MMA16816(acc[mt][nt], al[mt][0], al[mt][1], al[mt][2], al[mt][3], bh0, bh1); // lo*hi
            }
        }
    }

    // ---- spill k-half partials to smem [khalf][tok][e] ----
    {
        float* dst = lg + khalf * TMB * LSTR;
#pragma unroll
        for (int mt = 0; mt < 2; ++mt)
#pragma unroll
            for (int nt = 0; nt < 4; ++nt) {
                int tok = m0 + mt * 16 + r;
                int e   = n0 + nt * 8 + c0;
                dst[tok * LSTR + e]           = acc[mt][nt][0];
                dst[tok * LSTR + e + 1]       = acc[mt][nt][1];
                dst[(tok + 8) * LSTR + e]     = acc[mt][nt][2];
                dst[(tok + 8) * LSTR + e + 1] = acc[mt][nt][3];
            }
    }
    __syncthreads();

    // ---- epilogue: one token per thread (t < 64) ----
    if (t < TMB) {
        const long tokg = (long)blockIdx.x * TMB + t;
        const float f = 1.0f + 0.1f * sc[sidx_p[0]];
        const float* l0 = lg + t * LSTR;
        const float* l1 = lg + TMB * LSTR + t * LSTR;
        const float* nrow = noise + tokg * NEXP;
        const float4* nz = (const float4*)nrow;

        float lr[NEXP];
        float m = -1e30f;
#pragma unroll
        for (int q = 0; q < 16; ++q) {
            float4 nv = nz[q];
            float v0 = fmaf(f, l0[q * 4 + 0] + l1[q * 4 + 0], 0.1f * nv.x);
            float v1 = fmaf(f, l0[q * 4 + 1] + l1[q * 4 + 1], 0.1f * nv.y);
            float v2 = fmaf(f, l0[q * 4 + 2] + l1[q * 4 + 2], 0.1f * nv.z);
            float v3 = fmaf(f, l0[q * 4 + 3] + l1[q * 4 + 3], 0.1f * nv.w);
            lr[q * 4 + 0] = v0; lr[q * 4 + 1] = v1;
            lr[q * 4 + 2] = v2; lr[q * 4 + 3] = v3;
            m = fmaxf(m, fmaxf(fmaxf(v0, v1), fmaxf(v2, v3)));
        }

        // top-3 on raw logits (strict >: lowest index wins ties)
        float b1 = -1e30f, b2 = -1e30f, b3 = -1e30f;
        int   i1 = 0,      i2 = 0,      i3 = 0;
#pragma unroll
        for (int e = 0; e < NEXP; ++e) {
            float v = lr[e];
            if (v > b1)      { b3 = b2; i3 = i2; b2 = b1; i2 = i1; b1 = v; i1 = e; }
            else if (v > b2) { b3 = b2; i3 = i2; b2 = v;  i2 = e; }
            else if (v > b3) { b3 = v;  i3 = e; }
        }

        // exact-recompute guard (inlined, cold): near-ties decided with f32 dots
        if (__builtin_expect((b1 - b2 < TAU) || (b2 - b3 < TAU), 0)) {
            const float4* xa = (const float4*)(x + tokg * DDIM);
            const float4* wa = (const float4*)(W + (long)i1 * DDIM);
            const float4* wb = (const float4*)(W + (long)i2 * DDIM);
            const float4* wc = (const float4*)(W + (long)i3 * DDIM);
            float4 sA = make_float4(0.f,0.f,0.f,0.f);
            float4 sB = make_float4(0.f,0.f,0.f,0.f);
            float4 sC = make_float4(0.f,0.f,0.f,0.f);
            for (int i = 0; i < DDIM / 4; ++i) {
                float4 xv = xa[i];
                float4 w1 = wa[i], w2 = wb[i], w3 = wc[i];
                sA.x = fmaf(xv.x, w1.x, sA.x); sA.y = fmaf(xv.y, w1.y, sA.y);
                sA.z = fmaf(xv.z, w1.z, sA.z); sA.w = fmaf(xv.w, w1.w, sA.w);
                sB.x = fmaf(xv.x, w2.x, sB.x); sB.y = fmaf(xv.y, w2.y, sB.y);
                sB.z = fmaf(xv.z, w2.z, sB.z); sB.w = fmaf(xv.w, w2.w, sB.w);
                sC.x = fmaf(xv.x, w3.x, sC.x); sC.y = fmaf(xv.y, w3.y, sC.y);
                sC.z = fmaf(xv.z, w3.z, sC.z); sC.w = fmaf(xv.w, w3.w, sC.w);
            }
            float v[3];
            int   id[3] = {i1, i2, i3};
            v[0] = fmaf(f, (sA.x + sA.y) + (sA.z + sA.w), 0.1f * nrow[i1]);
            v[1] = fmaf(f, (sB.x + sB.y) + (sB.z + sB.w), 0.1f * nrow[i2]);
            v[2] = fmaf(f, (sC.x + sC.y) + (sC.z + sC.w), 0.1f * nrow[i3]);
            // sort 3 by (value desc, index asc): network (0,1),(1,2),(0,1)
#pragma unroll
            for (int s3 = 0; s3 < 3; ++s3) {
                int a = (s3 == 1) ? 1 : 0, b = a + 1;
                bool sw = (v[b] > v[a]) || (v[b] == v[a] && id[b] < id[a]);
                if (sw) {
                    float tv = v[a]; v[a] = v[b]; v[b] = tv;
                    int ti = id[a]; id[a] = id[b]; id[b] = ti;
                }
            }
            b1 = v[0]; i1 = id[0];
            b2 = v[1]; i2 = id[1];
        }

        float sum = 0.0f;
#pragma unroll
        for (int e = 0; e < NEXP; ++e) {
            float pb = __expf(lr[e] - m);
            lr[e] = pb;
            sum += pb;
        }
        const float inv = 1.0f / sum;
        const float p1  = __expf(b1 - m);
        const float p2  = __expf(b2 - m);
        const float wn  = 1.0f / (p1 + p2);
        const float w1v = p1 * wn, w2v = p2 * wn;

        float4* disp = (float4*)out + tokg * 16;
#pragma unroll
        for (int q = 0; q < 16; ++q) {
            float4 z = make_float4(0.f, 0.f, 0.f, 0.f);
            if ((i1 >> 2) == q) (&z.x)[i1 & 3] = w1v;
            if ((i2 >> 2) == q) (&z.x)[i2 & 3] = w2v;
            disp[q] = z;
        }
        if (do_probs) {
            float4* pr = (float4*)(out + (long)NTOK * NEXP) + tokg * 16;
#pragma unroll
            for (int q = 0; q < 16; ++q) {
                float4 z;
                z.x = lr[q * 4 + 0] * inv;
                z.y = lr[q * 4 + 1] * inv;
                z.z = lr[q * 4 + 2] * inv;
                z.w = lr[q * 4 + 3] * inv;
                pr[q] = z;
            }
        }
        if (do_idx) {
            float* ix = out + 2L * NTOK * NEXP + tokg * 2;
            ix[0] = (float)i1;
            ix[1] = (float)i2;
        }
    }
}

extern "C" void kernel_launch(void* const* d_in, const int* in_sizes, int n_in,
                              void* d_out, int out_size) {
    const float* x     = (const float*)d_in[0];
    const float* W     = (const float*)d_in[1];
    const float* sc    = (const float*)d_in[2];
    const float* noise = (const float*)d_in[3];
    const int*   sidx  = (const int*)d_in[4];
    float* out = (float*)d_out;

    const int do_probs = (out_size >= 2 * NTOK * NEXP) ? 1 : 0;
    const int do_idx   = (out_size >= 2 * NTOK * NEXP + 2 * NTOK) ? 1 : 0;

    moe_main<<<NBLK, 256>>>(x, W, sc, noise, sidx, out, do_probs, do_idx);
}

// round 11
// speedup vs baseline: 1.0152x; 1.0152x over previous
#include <cuda_runtime.h>
#include <cuda_bf16.h>

typedef unsigned int u32;

#define NTOK 16384
#define DDIM 2048
#define NEXP 64
#define TMB  64              // tokens per CTA
#define NBLK (NTOK/TMB)      // 256
#define LSTR 66
#define KSTEPS 64            // k16 steps per k-half (1024/16)
#define TAU   1e-4f

// pack (v0 -> low half, v1 -> high half)
static __device__ __forceinline__ u32 pack_bf16(float v0, float v1) {
    u32 r; asm("cvt.rn.bf16x2.f32 %0, %1, %2;" : "=r"(r) : "f"(v1), "f"(v0)); return r;
}
// split float2 -> (hi bf16x2, lo bf16x2)
static __device__ __forceinline__ void split2(float2 v, u32& hi, u32& lo) {
    hi = pack_bf16(v.x, v.y);
    float f0 = __uint_as_float(hi << 16);
    float f1 = __uint_as_float(hi & 0xffff0000u);
    lo = pack_bf16(v.x - f0, v.y - f1);
}

#define MMA16816(d, a0,a1,a2,a3, b0, b1) \
    asm volatile("mma.sync.aligned.m16n8k16.row.col.f32.bf16.bf16.f32 " \
        "{%0,%1,%2,%3}, {%4,%5,%6,%7}, {%8,%9}, {%0,%1,%2,%3};" \
        : "+f"((d)[0]),"+f"((d)[1]),"+f"((d)[2]),"+f"((d)[3]) \
        : "r"(a0),"r"(a1),"r"(a2),"r"(a3),"r"(b0),"r"(b1))

__global__ __launch_bounds__(256, 2) void moe_main(
    const float* __restrict__ x,
    const float* __restrict__ W,
    const float* __restrict__ sc,
    const float* __restrict__ noise,
    const int*   __restrict__ sidx_p,
    float*       __restrict__ out,
    int do_probs, int do_idx)
{
    __shared__ float lg[2 * TMB * LSTR];   // per-k-half partial logits

    const int t   = threadIdx.x;
    const int wid = t >> 5;
    const int lid = t & 31;

    const int khalf = wid >> 2;            // 0 or 1: k-range [khalf*1024, +1024)
    const int m0    = ((wid >> 1) & 1) * 32;
    const int n0    = (wid & 1) * 32;

    const int r  = lid >> 2;               // fragment row within m8/n8
    const int c0 = (lid & 3) * 2;          // fragment k pair base

    // A row pointers: rows m0+r (+8, +16, +24), k base = khalf*1024 + c0
    const float* xbase = x + (long)blockIdx.x * TMB * DDIM + khalf * 1024 + c0;
    const float* arp[4];
#pragma unroll
    for (int i = 0; i < 4; ++i) arp[i] = xbase + (long)(m0 + r + i * 8) * DDIM;

    // B row pointers: experts n0 + (lid>>2) + nt*8
    const float* wbase = W + khalf * 1024 + c0;
    const float* wrp[4];
#pragma unroll
    for (int i = 0; i < 4; ++i) wrp[i] = wbase + (long)(n0 + (lid >> 2) + i * 8) * DDIM;

    float acc[2][4][4];
#pragma unroll
    for (int mt = 0; mt < 2; ++mt)
#pragma unroll
        for (int nt = 0; nt < 4; ++nt)
#pragma unroll
            for (int q = 0; q < 4; ++q) acc[mt][nt][q] = 0.0f;

    // A raw buffer for current step (prefetched)
    float2 ab[8];
#pragma unroll
    for (int mt = 0; mt < 2; ++mt) {
        ab[mt * 4 + 0] = *(const float2*)(arp[mt * 2 + 0]);
        ab[mt * 4 + 1] = *(const float2*)(arp[mt * 2 + 1]);
        ab[mt * 4 + 2] = *(const float2*)(arp[mt * 2 + 0] + 8);
        ab[mt * 4 + 3] = *(const float2*)(arp[mt * 2 + 1] + 8);
    }

#pragma unroll 2
    for (int s = 0; s < KSTEPS; ++s) {
        const int k = s * 16;

        // 1) issue all B loads for this step (mostly L2 hits)
        float2 brw[8];
#pragma unroll
        for (int nt = 0; nt < 4; ++nt) {
            brw[nt * 2 + 0] = *(const float2*)(wrp[nt] + k);
            brw[nt * 2 + 1] = *(const float2*)(wrp[nt] + k + 8);
        }

        // 2) convert A (from prefetch buffer)
        u32 ah[2][4], al[2][4];
#pragma unroll
        for (int mt = 0; mt < 2; ++mt)
#pragma unroll
            for (int q = 0; q < 4; ++q)
                split2(ab[mt * 4 + q], ah[mt][q], al[mt][q]);

        // 3) prefetch A for next step (lands under the MMA block)
        if (s + 1 < KSTEPS) {
            const int kn = k + 16;
#pragma unroll
            for (int mt = 0; mt < 2; ++mt) {
                ab[mt * 4 + 0] = *(const float2*)(arp[mt * 2 + 0] + kn);
                ab[mt * 4 + 1] = *(const float2*)(arp[mt * 2 + 1] + kn);
                ab[mt * 4 + 2] = *(const float2*)(arp[mt * 2 + 0] + kn + 8);
                ab[mt * 4 + 3] = *(const float2*)(arp[mt * 2 + 1] + kn + 8);
            }
        }

        // 4) convert B per n8 tile and issue MMAs
#pragma unroll
        for (int nt = 0; nt < 4; ++nt) {
            u32 bh0, bh1, bl0, bl1;
            split2(brw[nt * 2 + 0], bh0, bl0);
            split2(brw[nt * 2 + 1], bh1, bl1);
#pragma unroll
            for (int mt = 0; mt < 2; ++mt) {
                MMA16816(acc[mt][nt], ah[mt][0], ah[mt][1], ah[mt][2], ah[mt][3], bh0, bh1); // hi*hi
                MMA16816(acc[mt][nt], ah[mt][0], ah[mt][1], ah[mt][2], ah[mt][3], bl0, bl1); // hi*lo
                MMA16816(acc[mt][nt], al[mt][0], al[mt][1], al[mt][2], al[mt][3], bh0, bh1); // lo*hi
            }
        }
    }

    // ---- spill k-half partials to smem [khalf][tok][e] ----
    {
        float* dst = lg + khalf * TMB * LSTR;
#pragma unroll
        for (int mt = 0; mt < 2; ++mt)
#pragma unroll
            for (int nt = 0; nt < 4; ++nt) {
                int tok = m0 + mt * 16 + r;
                int e   = n0 + nt * 8 + c0;
                dst[tok * LSTR + e]           = acc[mt][nt][0];
                dst[tok * LSTR + e + 1]       = acc[mt][nt][1];
                dst[(tok + 8) * LSTR + e]     = acc[mt][nt][2];
                dst[(tok + 8) * LSTR + e + 1] = acc[mt][nt][3];
            }
    }
    __syncthreads();

    // ---- epilogue: one token per thread (t < 64) ----
    if (t < TMB) {
        const long tokg = (long)blockIdx.x * TMB + t;
        const float f = 1.0f + 0.1f * sc[sidx_p[0]];
        const float* l0 = lg + t * LSTR;
        const float* l1 = lg + TMB * LSTR + t * LSTR;
        const float* nrow = noise + tokg * NEXP;
        const float4* nz = (const float4*)nrow;

        float lr[NEXP];
        float m = -1e30f;
#pragma unroll
        for (int q = 0; q < 16; ++q) {
            float4 nv = nz[q];
            float v0 = fmaf(f, l0[q * 4 + 0] + l1[q * 4 + 0], 0.1f * nv.x);
            float v1 = fmaf(f, l0[q * 4 + 1] + l1[q * 4 + 1], 0.1f * nv.y);
            float v2 = fmaf(f, l0[q * 4 + 2] + l1[q * 4 + 2], 0.1f * nv.z);
            float v3 = fmaf(f, l0[q * 4 + 3] + l1[q * 4 + 3], 0.1f * nv.w);
            lr[q * 4 + 0] = v0; lr[q * 4 + 1] = v1;
            lr[q * 4 + 2] = v2; lr[q * 4 + 3] = v3;
            m = fmaxf(m, fmaxf(fmaxf(v0, v1), fmaxf(v2, v3)));
        }

        // top-3 on raw logits (strict >: lowest index wins ties)
        float b1 = -1e30f, b2 = -1e30f, b3 = -1e30f;
        int   i1 = 0,      i2 = 0,      i3 = 0;
#pragma unroll
        for (int e = 0; e < NEXP; ++e) {
            float v = lr[e];
            if (v > b1)      { b3 = b2; i3 = i2; b2 = b1; i2 = i1; b1 = v; i1 = e; }
            else if (v > b2) { b3 = b2; i3 = i2; b2 = v;  i2 = e; }
            else if (v > b3) { b3 = v;  i3 = e; }
        }

        // exact-recompute guard (inlined, cold): near-ties decided with f32 dots
        if (__builtin_expect((b1 - b2 < TAU) || (b2 - b3 < TAU), 0)) {
            const float4* xa = (const float4*)(x + tokg * DDIM);
            const float4* wa = (const float4*)(W + (long)i1 * DDIM);
            const float4* wb = (const float4*)(W + (long)i2 * DDIM);
            const float4* wc = (const float4*)(W + (long)i3 * DDIM);
            float4 sA = make_float4(0.f,0.f,0.f,0.f);
            float4 sB = make_float4(0.f,0.f,0.f,0.f);
            float4 sC = make_float4(0.f,0.f,0.f,0.f);
            for (int i = 0; i < DDIM / 4; ++i) {
                float4 xv = xa[i];
                float4 w1 = wa[i], w2 = wb[i], w3 = wc[i];
                sA.x = fmaf(xv.x, w1.x, sA.x); sA.y = fmaf(xv.y, w1.y, sA.y);
                sA.z = fmaf(xv.z, w1.z, sA.z); sA.w = fmaf(xv.w, w1.w, sA.w);
                sB.x = fmaf(xv.x, w2.x, sB.x); sB.y = fmaf(xv.y, w2.y, sB.y);
                sB.z = fmaf(xv.z, w2.z, sB.z); sB.w = fmaf(xv.w, w2.w, sB.w);
                sC.x = fmaf(xv.x, w3.x, sC.x); sC.y = fmaf(xv.y, w3.y, sC.y);
                sC.z = fmaf(xv.z, w3.z, sC.z); sC.w = fmaf(xv.w, w3.w, sC.w);
            }
            float v[3];
            int   id[3] = {i1, i2, i3};
            v[0] = fmaf(f, (sA.x + sA.y) + (sA.z + sA.w), 0.1f * nrow[i1]);
            v[1] = fmaf(f, (sB.x + sB.y) + (sB.z + sB.w), 0.1f * nrow[i2]);
            v[2] = fmaf(f, (sC.x + sC.y) + (sC.z + sC.w), 0.1f * nrow[i3]);
            // sort 3 by (value desc, index asc): network (0,1),(1,2),(0,1)
#pragma unroll
            for (int s3 = 0; s3 < 3; ++s3) {
                int a = (s3 == 1) ? 1 : 0, b = a + 1;
                bool sw = (v[b] > v[a]) || (v[b] == v[a] && id[b] < id[a]);
                if (sw) {
                    float tv = v[a]; v[a] = v[b]; v[b] = tv;
                    int ti = id[a]; id[a] = id[b]; id[b] = ti;
                }
            }
            b1 = v[0]; i1 = id[0];
            b2 = v[1]; i2 = id[1];
        }

        float sum = 0.0f;
#pragma unroll
        for (int e = 0; e < NEXP; ++e) {
            float pb = __expf(lr[e] - m);
            lr[e] = pb;
            sum += pb;
        }
        const float inv = 1.0f / sum;
        const float p1  = __expf(b1 - m);
        const float p2  = __expf(b2 - m);
        const float wn  = 1.0f / (p1 + p2);
        const float w1v = p1 * wn, w2v = p2 * wn;

        float4* disp = (float4*)out + tokg * 16;
#pragma unroll
        for (int q = 0; q < 16; ++q) {
            float4 z = make_float4(0.f, 0.f, 0.f, 0.f);
            if ((i1 >> 2) == q) (&z.x)[i1 & 3] = w1v;
            if ((i2 >> 2) == q) (&z.x)[i2 & 3] = w2v;
            disp[q] = z;
        }
        if (do_probs) {
            float4* pr = (float4*)(out + (long)NTOK * NEXP) + tokg * 16;
#pragma unroll
            for (int q = 0; q < 16; ++q) {
                float4 z;
                z.x = lr[q * 4 + 0] * inv;
                z.y = lr[q * 4 + 1] * inv;
                z.z = lr[q * 4 + 2] * inv;
                z.w = lr[q * 4 + 3] * inv;
                pr[q] = z;
            }
        }
        if (do_idx) {
            float* ix = out + 2L * NTOK * NEXP + tokg * 2;
            ix[0] = (float)i1;
            ix[1] = (float)i2;
        }
    }
}

extern "C" void kernel_launch(void* const* d_in, const int* in_sizes, int n_in,
                              void* d_out, int out_size) {
    const float* x     = (const float*)d_in[0];
    const float* W     = (const float*)d_in[1];
    const float* sc    = (const float*)d_in[2];
    const float* noise = (const float*)d_in[3];
    const int*   sidx  = (const int*)d_in[4];
    float* out = (float*)d_out;

    const int do_probs = (out_size >= 2 * NTOK * NEXP) ? 1 : 0;
    const int do_idx   = (out_size >= 2 * NTOK * NEXP + 2 * NTOK) ? 1 : 0;

    moe_main<<<NBLK, 256>>>(x, W, sc, noise, sidx, out, do_probs, do_idx);
}

// round 13
// speedup vs baseline: 1.0743x; 1.0582x over previous
#include <cuda_runtime.h>
#include <cuda_bf16.h>

typedef unsigned int u32;

#define NTOK 16384
#define DDIM 2048
#define NEXP 64
#define TMB  64              // tokens per CTA
#define KC   64
#define NCHUNK (DDIM/KC)     // 32
#define NBLK (NTOK/TMB)      // 256
#define LSTR 66
#define TAU  1e-4f

// double-buffered smem layout (bytes): each tile 64x64 bf16 = 8KB
#define XHI(p) ((p) * 8192)
#define XLO(p) (16384 + (p) * 8192)
#define WHI(p) (32768 + (p) * 8192)
#define WLO(p) (49152 + (p) * 8192)
#define SMEM_BYTES 65536

static __device__ __forceinline__ u32 smem_u32(const void* p) {
    u32 a; asm("{ .reg .u64 t; cvta.to.shared.u64 t, %1; cvt.u32.u64 %0, t; }" : "=r"(a) : "l"(p));
    return a;
}
// pack (v0 -> low half, v1 -> high half)
static __device__ __forceinline__ u32 pack_bf16(float v0, float v1) {
    u32 r; asm("cvt.rn.bf16x2.f32 %0, %1, %2;" : "=r"(r) : "f"(v1), "f"(v0)); return r;
}

#define LDM_X4(r0,r1,r2,r3, addr) \
    asm volatile("ldmatrix.sync.aligned.m8n8.x4.shared.b16 {%0,%1,%2,%3}, [%4];" \
        : "=r"(r0),"=r"(r1),"=r"(r2),"=r"(r3) : "r"(addr))

#define MMA16816(d, a, b0, b1) \
    asm volatile("mma.sync.aligned.m16n8k16.row.col.f32.bf16.bf16.f32 " \
        "{%0,%1,%2,%3}, {%4,%5,%6,%7}, {%8,%9}, {%0,%1,%2,%3};" \
        : "+f"((d)[0]),"+f"((d)[1]),"+f"((d)[2]),"+f"((d)[3]) \
        : "r"((a)[0]),"r"((a)[1]),"r"((a)[2]),"r"((a)[3]),"r"(b0),"r"(b1))

__global__ __launch_bounds__(256, 2) void moe_main(
    const float* __restrict__ x,
    const float* __restrict__ W,
    const float* __restrict__ sc,
    const float* __restrict__ noise,
    const int*   __restrict__ sidx_p,
    float*       __restrict__ out,
    int do_probs, int do_idx)
{
    extern __shared__ __align__(16) char dsm[];
    const u32 sb = smem_u32(dsm);

    const int t   = threadIdx.x;
    const int wid = t >> 5;
    const int lid = t & 31;

    // warp tile: khalf = wid>>2 (covers 2 of the 4 k16 steps), m0 in {0,32}, n0 in {0,32}
    const int khalf = wid >> 2;
    const int m0    = ((wid >> 1) & 1) * 32;
    const int n0    = (wid & 1) * 32;
    const int tokA = lid & 15;
    const int kqA  = lid >> 4;
    const int eB   = (lid & 7) + ((lid >> 4) << 3);
    const int kqB  = (lid >> 3) & 1;

    // loaders: x (64 tok) and W (64 exp) tiles are 64x64 f32 per chunk;
    // thread covers row = t>>2, k-quarter (t&3)*16
    const int lrow = t >> 2;
    const int lq   = t & 3;
    const float* xg = x + (long)blockIdx.x * TMB * DDIM + (long)lrow * DDIM + lq * 16;
    const float* wg = W + (long)lrow * DDIM + lq * 16;
    const u32 tsb = (u32)lrow * 128u + (u32)lq * 32u;
    const u32 swz = ((u32)lrow & 7u) << 4;

    float acc[2][4][4];
#pragma unroll
    for (int mt = 0; mt < 2; ++mt)
#pragma unroll
        for (int j = 0; j < 4; ++j)
#pragma unroll
            for (int r = 0; r < 4; ++r) acc[mt][j][r] = 0.0f;

    float4 xr[4], wr[4];

    auto conv8 = [&](float4 a, float4 b, uint4& hi, uint4& lo) {
        u32 h01 = pack_bf16(a.x, a.y);
        u32 h23 = pack_bf16(a.z, a.w);
        u32 h45 = pack_bf16(b.x, b.y);
        u32 h67 = pack_bf16(b.z, b.w);
        float f0 = __uint_as_float(h01 << 16), f1 = __uint_as_float(h01 & 0xffff0000u);
        float f2 = __uint_as_float(h23 << 16), f3 = __uint_as_float(h23 & 0xffff0000u);
        float f4 = __uint_as_float(h45 << 16), f5 = __uint_as_float(h45 & 0xffff0000u);
        float f6 = __uint_as_float(h67 << 16), f7 = __uint_as_float(h67 & 0xffff0000u);
        hi = make_uint4(h01, h23, h45, h67);
        lo = make_uint4(pack_bf16(a.x - f0, a.y - f1),
                        pack_bf16(a.z - f2, a.w - f3),
                        pack_bf16(b.x - f4, b.y - f5),
                        pack_bf16(b.z - f6, b.w - f7));
    };

    auto store_tiles = [&](int p) {
#pragma unroll
        for (int qq = 0; qq < 2; ++qq) {
            uint4 hi, lo;
            u32 sw = (tsb + (u32)qq * 16u) ^ swz;
            conv8(xr[2 * qq], xr[2 * qq + 1], hi, lo);
            *(uint4*)(dsm + XHI(p) + sw) = hi;
            *(uint4*)(dsm + XLO(p) + sw) = lo;
            conv8(wr[2 * qq], wr[2 * qq + 1], hi, lo);
            *(uint4*)(dsm + WHI(p) + sw) = hi;
            *(uint4*)(dsm + WLO(p) + sw) = lo;
        }
    };

    auto load_chunk = [&](int c) {
        const float* xb = xg + c * KC;
        const float* wb = wg + c * KC;
#pragma unroll
        for (int q = 0; q < 4; ++q) xr[q] = *(const float4*)(xb + q * 4);
#pragma unroll
        for (int q = 0; q < 4; ++q) wr[q] = *(const float4*)(wb + q * 4);
    };

    // prologue
    load_chunk(0);
    store_tiles(0);
    load_chunk(1);
    __syncthreads();

#pragma unroll 1
    for (int it = 0; it < NCHUNK; ++it) {
        const int p = it & 1;

        if (it + 1 < NCHUNK) store_tiles(p ^ 1);   // stage chunk it+1
        if (it + 2 < NCHUNK) load_chunk(it + 2);   // LDG chunk it+2 under MMAs

        // this warp covers kk in {khalf*2, khalf*2+1}
#pragma unroll
        for (int kk2 = 0; kk2 < 2; ++kk2) {
            const int kk = khalf * 2 + kk2;
            u32 ah[2][4], al[2][4];
#pragma unroll
            for (int mt = 0; mt < 2; ++mt) {
                int tok = m0 + mt * 16 + tokA;
                u32 sw = (u32)(((kk * 2 + kqA) ^ (tokA & 7)) << 4);
                u32 aaddr = sb + XHI(p) + (u32)tok * 128u + sw;
                LDM_X4(ah[mt][0], ah[mt][1], ah[mt][2], ah[mt][3], aaddr);
                LDM_X4(al[mt][0], al[mt][1], al[mt][2], al[mt][3], aaddr + 16384u);
            }
#pragma unroll
            for (int ng = 0; ng < 2; ++ng) {
                u32 bh[4], bl[4];
                int ef = n0 + ng * 16 + eB;
                u32 sw = (u32)(((kk * 2 + kqB) ^ (eB & 7)) << 4);
                u32 baddr = sb + WHI(p) + (u32)ef * 128u + sw;
                LDM_X4(bh[0], bh[1], bh[2], bh[3], baddr);
                LDM_X4(bl[0], bl[1], bl[2], bl[3], baddr + 16384u);
#pragma unroll
                for (int mt = 0; mt < 2; ++mt) {
#pragma unroll
                    for (int jl = 0; jl < 2; ++jl) {
                        float* d = acc[mt][ng * 2 + jl];
                        MMA16816(d, ah[mt], bh[jl * 2], bh[jl * 2 + 1]); // hi*hi
                        MMA16816(d, ah[mt], bl[jl * 2], bl[jl * 2 + 1]); // hi*lo
                        MMA16816(d, al[mt], bh[jl * 2], bh[jl * 2 + 1]); // lo*hi
                    }
                }
            }
        }

        __syncthreads();
    }

    // ---- spill k-half partials into (reused) dynamic smem: [khalf][tok][e] ----
    {
        float* lg = (float*)dsm + khalf * TMB * LSTR;
        const int r  = lid >> 2;
        const int c0 = (lid & 3) * 2;
#pragma unroll
        for (int mt = 0; mt < 2; ++mt)
#pragma unroll
            for (int nt = 0; nt < 4; ++nt) {
                int tok = m0 + mt * 16 + r;
                int e   = n0 + nt * 8 + c0;
                lg[tok * LSTR + e]           = acc[mt][nt][0];
                lg[tok * LSTR + e + 1]       = acc[mt][nt][1];
                lg[(tok + 8) * LSTR + e]     = acc[mt][nt][2];
                lg[(tok + 8) * LSTR + e + 1] = acc[mt][nt][3];
            }
    }
    __syncthreads();

    // ---- epilogue: one token per thread (t < 64) ----
    if (t < TMB) {
        const long tokg = (long)blockIdx.x * TMB + t;
        const float f = 1.0f + 0.1f * sc[sidx_p[0]];
        const float* l0 = (const float*)dsm + t * LSTR;
        const float* l1 = (const float*)dsm + TMB * LSTR + t * LSTR;
        const float* nrow = noise + tokg * NEXP;
        const float4* nz = (const float4*)nrow;

        float lr[NEXP];
        float m = -1e30f;
#pragma unroll
        for (int q = 0; q < 16; ++q) {
            float4 nv = nz[q];
            float v0 = fmaf(f, l0[q * 4 + 0] + l1[q * 4 + 0], 0.1f * nv.x);
            float v1 = fmaf(f, l0[q * 4 + 1] + l1[q * 4 + 1], 0.1f * nv.y);
            float v2 = fmaf(f, l0[q * 4 + 2] + l1[q * 4 + 2], 0.1f * nv.z);
            float v3 = fmaf(f, l0[q * 4 + 3] + l1[q * 4 + 3], 0.1f * nv.w);
            lr[q * 4 + 0] = v0; lr[q * 4 + 1] = v1;
            lr[q * 4 + 2] = v2; lr[q * 4 + 3] = v3;
            m = fmaxf(m, fmaxf(fmaxf(v0, v1), fmaxf(v2, v3)));
        }

        // top-3 on raw logits (strict >: lowest index wins ties)
        float b1 = -1e30f, b2 = -1e30f, b3 = -1e30f;
        int   i1 = 0,      i2 = 0,      i3 = 0;
#pragma unroll
        for (int e = 0; e < NEXP; ++e) {
            float v = lr[e];
            if (v > b1)      { b3 = b2; i3 = i2; b2 = b1; i2 = i1; b1 = v; i1 = e; }
            else if (v > b2) { b3 = b2; i3 = i2; b2 = v;  i2 = e; }
            else if (v > b3) { b3 = v;  i3 = e; }
        }

        // exact-recompute guard (inlined, cold): near-ties decided with f32 dots
        if (__builtin_expect((b1 - b2 < TAU) || (b2 - b3 < TAU), 0)) {
            const float4* xa = (const float4*)(x + tokg * DDIM);
            const float4* wa = (const float4*)(W + (long)i1 * DDIM);
            const float4* wb = (const float4*)(W + (long)i2 * DDIM);
            const float4* wc = (const float4*)(W + (long)i3 * DDIM);
            float4 sA = make_float4(0.f,0.f,0.f,0.f);
            float4 sB = make_float4(0.f,0.f,0.f,0.f);
            float4 sC = make_float4(0.f,0.f,0.f,0.f);
            for (int i = 0; i < DDIM / 4; ++i) {
                float4 xv = xa[i];
                float4 w1 = wa[i], w2 = wb[i], w3 = wc[i];
                sA.x = fmaf(xv.x, w1.x, sA.x); sA.y = fmaf(xv.y, w1.y, sA.y);
                sA.z = fmaf(xv.z, w1.z, sA.z); sA.w = fmaf(xv.w, w1.w, sA.w);
                sB.x = fmaf(xv.x, w2.x, sB.x); sB.y = fmaf(xv.y, w2.y, sB.y);
                sB.z = fmaf(xv.z, w2.z, sB.z); sB.w = fmaf(xv.w, w2.w, sB.w);
                sC.x = fmaf(xv.x, w3.x, sC.x); sC.y = fmaf(xv.y, w3.y, sC.y);
                sC.z = fmaf(xv.z, w3.z, sC.z); sC.w = fmaf(xv.w, w3.w, sC.w);
            }
            float v[3];
            int   id[3] = {i1, i2, i3};
            v[0] = fmaf(f, (sA.x + sA.y) + (sA.z + sA.w), 0.1f * nrow[i1]);
            v[1] = fmaf(f, (sB.x + sB.y) + (sB.z + sB.w), 0.1f * nrow[i2]);
            v[2] = fmaf(f, (sC.x + sC.y) + (sC.z + sC.w), 0.1f * nrow[i3]);
            // sort 3 by (value desc, index asc): network (0,1),(1,2),(0,1)
#pragma unroll
            for (int s3 = 0; s3 < 3; ++s3) {
                int a = (s3 == 1) ? 1 : 0, b = a + 1;
                bool sw = (v[b] > v[a]) || (v[b] == v[a] && id[b] < id[a]);
                if (sw) {
                    float tv = v[a]; v[a] = v[b]; v[b] = tv;
                    int ti = id[a]; id[a] = id[b]; id[b] = ti;
                }
            }
            b1 = v[0]; i1 = id[0];
            b2 = v[1]; i2 = id[1];
        }

        float sum = 0.0f;
#pragma unroll
        for (int e = 0; e < NEXP; ++e) {
            float pb = __expf(lr[e] - m);
            lr[e] = pb;
            sum += pb;
        }
        const float inv = 1.0f / sum;
        const float p1  = __expf(b1 - m);
        const float p2  = __expf(b2 - m);
        const float wn  = 1.0f / (p1 + p2);
        const float w1v = p1 * wn, w2v = p2 * wn;

        float4* disp = (float4*)out + tokg * 16;
#pragma unroll
        for (int q = 0; q < 16; ++q) {
            float4 z = make_float4(0.f, 0.f, 0.f, 0.f);
            if ((i1 >> 2) == q) (&z.x)[i1 & 3] = w1v;
            if ((i2 >> 2) == q) (&z.x)[i2 & 3] = w2v;
            disp[q] = z;
        }
        if (do_probs) {
            float4* pr = (float4*)(out + (long)NTOK * NEXP) + tokg * 16;
#pragma unroll
            for (int q = 0; q < 16; ++q) {
                float4 z;
                z.x = lr[q * 4 + 0] * inv;
                z.y = lr[q * 4 + 1] * inv;
                z.z = lr[q * 4 + 2] * inv;
                z.w = lr[q * 4 + 3] * inv;
                pr[q] = z;
            }
        }
        if (do_idx) {
            float* ix = out + 2L * NTOK * NEXP + tokg * 2;
            ix[0] = (float)i1;
            ix[1] = (float)i2;
        }
    }
}

extern "C" void kernel_launch(void* const* d_in, const int* in_sizes, int n_in,
                              void* d_out, int out_size) {
    const float* x     = (const float*)d_in[0];
    const float* W     = (const float*)d_in[1];
    const float* sc    = (const float*)d_in[2];
    const float* noise = (const float*)d_in[3];
    const int*   sidx  = (const int*)d_in[4];
    float* out = (float*)d_out;

    const int do_probs = (out_size >= 2 * NTOK * NEXP) ? 1 : 0;
    const int do_idx   = (out_size >= 2 * NTOK * NEXP + 2 * NTOK) ? 1 : 0;

    cudaFuncSetAttribute(moe_main, cudaFuncAttributeMaxDynamicSharedMemorySize, SMEM_BYTES);
    moe_main<<<NBLK, 256, SMEM_BYTES>>>(x, W, sc, noise, sidx, out, do_probs, do_idx);
}